// round 4
// baseline (speedup 1.0000x reference)
#include <cuda_runtime.h>
#include <cuda_bf16.h>

#define PLANES 48  // B*C = 16*3

// ---------------- static device scratch (no allocations allowed) ----------------
__device__ float g_d1[2][PLANES * 256 * 256];  // level-0 downs == level-1 currents
__device__ float g_d2[2][PLANES * 128 * 128];  // level-1 downs == level-2 currents
__device__ float g_d3[2][PLANES * 64 * 64];    // level-2 downs
__device__ double g_acc[3];                    // per-level |.| sums

// reflect index (numpy 'reflect', pad<=2): -1->1, -2->2, n->n-2, n+1->n-3
__device__ __forceinline__ int refl(int p, int n) {
    p = (p < 0) ? -p : p;
    return (p >= n) ? (2 * n - 2 - p) : p;
}

__global__ void zero_acc_kernel() {
    if (threadIdx.x < 3) g_acc[threadIdx.x] = 0.0;
}

// -------------------------------------------------------------------------------
// down_kernel: down[i,j] = sum_{ky,kx} g[ky]g[kx]/256 * cur[refl(2i+ky-2)][refl(2j+kx-2)]
// block (32,8) -> 32x8 down pixels; smem cur tile 19x67.
// grid: (N2/32, N2/8, 96)  z<48 -> image A, else image B
// -------------------------------------------------------------------------------
__global__ __launch_bounds__(256) void down_kernel(int lvl,
                                                   const float* __restrict__ extA,
                                                   const float* __restrict__ extB) {
    int N;
    const float *bA, *bB;
    float *oA, *oB;
    if (lvl == 0)      { N = 512; bA = extA;     bB = extB;     oA = g_d1[0]; oB = g_d1[1]; }
    else if (lvl == 1) { N = 256; bA = g_d1[0];  bB = g_d1[1];  oA = g_d2[0]; oB = g_d2[1]; }
    else               { N = 128; bA = g_d2[0];  bB = g_d2[1];  oA = g_d3[0]; oB = g_d3[1]; }
    const int N2 = N >> 1;

    const int z = blockIdx.z;
    const int p = (z < PLANES) ? z : z - PLANES;
    const float* cur = ((z < PLANES) ? bA : bB) + (size_t)p * N * N;
    float* dn        = ((z < PLANES) ? oA : oB) + (size_t)p * N2 * N2;

    __shared__ float s[19][68];
    const int i0 = blockIdx.y * 8, j0 = blockIdx.x * 32;
    const int r0 = 2 * i0 - 2, c0 = 2 * j0 - 2;
    const int tid = threadIdx.y * 32 + threadIdx.x;

    for (int idx = tid; idx < 19 * 67; idx += 256) {
        int r = idx / 67, c = idx - r * 67;
        s[r][c] = __ldg(&cur[(size_t)refl(r0 + r, N) * N + refl(c0 + c, N)]);
    }
    __syncthreads();

    const int li = threadIdx.y, lj = threadIdx.x;
    float acc = 0.f;
#pragma unroll
    for (int ky = 0; ky < 5; ky++) {
        const float gy = (ky == 0 || ky == 4) ? 1.f : ((ky == 2) ? 6.f : 4.f);
        float rs = s[2 * li + ky][2 * lj + 0] + s[2 * li + ky][2 * lj + 4]
                 + 4.f * (s[2 * li + ky][2 * lj + 1] + s[2 * li + ky][2 * lj + 3])
                 + 6.f *  s[2 * li + ky][2 * lj + 2];
        acc += gy * rs;
    }
    dn[(size_t)(i0 + li) * N2 + (j0 + lj)] = acc * (1.0f / 256.0f);
}

// -------------------------------------------------------------------------------
// loss_kernel: fused  up -> diff -> |GX conv| + |GY conv| -> | m_in - m_tg | -> sum
// Output grid is (N+2)x(N+2).  Block (32,16) computes a 32x16 output tile.
// smem: diff tile 2x18x34 (computed here), down window 2x13x21.
// grid: (ceil((N+2)/32), ceil((N+2)/16), 48)
// -------------------------------------------------------------------------------
#define TY 16
#define TX 32
#define DR 13
#define DC 21

__global__ __launch_bounds__(512) void loss_kernel(int lvl,
                                                   const float* __restrict__ extA,
                                                   const float* __restrict__ extB) {
    int N;
    const float *cA, *cB, *dA, *dB;
    if (lvl == 0)      { N = 512; cA = extA;    cB = extB;    dA = g_d1[0]; dB = g_d1[1]; }
    else if (lvl == 1) { N = 256; cA = g_d1[0]; cB = g_d1[1]; dA = g_d2[0]; dB = g_d2[1]; }
    else               { N = 128; cA = g_d2[0]; cB = g_d2[1]; dA = g_d3[0]; dB = g_d3[1]; }
    const int N2 = N >> 1;

    const int p = blockIdx.z;
    const float* cur0 = cA + (size_t)p * N * N;
    const float* cur1 = cB + (size_t)p * N * N;
    const float* dn0  = dA + (size_t)p * N2 * N2;
    const float* dn1  = dB + (size_t)p * N2 * N2;

    __shared__ float s_dn[2][DR][DC];
    __shared__ float s_df[2][TY + 2][TX + 3];
    __shared__ float warpsum[16];

    const int oy0 = blockIdx.y * TY, ox0 = blockIdx.x * TX;
    const int R0 = max(0, (oy0 - 4) >> 1);
    const int C0 = max(0, (ox0 - 4) >> 1);
    const int tid = threadIdx.y * TX + threadIdx.x;
    const int NT = TY * TX;

    // load down windows (clamped rows/cols — clamp slots are never read by valid lookups)
    for (int idx = tid; idx < 2 * DR * DC; idx += NT) {
        int img = idx / (DR * DC);
        int rem = idx - img * (DR * DC);
        int r = rem / DC, c = rem - r * DC;
        int rr = min(R0 + r, N2 - 1);
        int cc = min(C0 + c, N2 - 1);
        const float* dn = img ? dn1 : dn0;
        s_dn[img][r][c] = __ldg(&dn[(size_t)rr * N2 + cc]);
    }
    __syncthreads();

    // compute diff tile: diff(h,w) = cur(h,w) - up(h,w)
    for (int idx = tid; idx < (TY + 2) * (TX + 2); idx += NT) {
        int i = idx / (TX + 2), j = idx - i * (TX + 2);
        int h = refl(oy0 - 2 + i, N);
        int w = refl(ox0 - 2 + j, N);

        // parity-decomposed separable up taps ([1,4,6,4,1]/8 per dim on interleaved grid)
        int sr[3]; float wr[3];
        if (h & 1) { sr[0] = refl(h - 1, N) >> 1; wr[0] = 4.f;
                     sr[1] = refl(h + 1, N) >> 1; wr[1] = 4.f;
                     sr[2] = sr[0];               wr[2] = 0.f; }
        else       { sr[0] = refl(h - 2, N) >> 1; wr[0] = 1.f;
                     sr[1] = h >> 1;              wr[1] = 6.f;
                     sr[2] = refl(h + 2, N) >> 1; wr[2] = 1.f; }
        int sc[3]; float wc[3];
        if (w & 1) { sc[0] = refl(w - 1, N) >> 1; wc[0] = 4.f;
                     sc[1] = refl(w + 1, N) >> 1; wc[1] = 4.f;
                     sc[2] = sc[0];               wc[2] = 0.f; }
        else       { sc[0] = refl(w - 2, N) >> 1; wc[0] = 1.f;
                     sc[1] = w >> 1;              wc[1] = 6.f;
                     sc[2] = refl(w + 2, N) >> 1; wc[2] = 1.f; }
#pragma unroll
        for (int t = 0; t < 3; t++) {
            sr[t] = min(max(sr[t] - R0, 0), DR - 1);
            sc[t] = min(max(sc[t] - C0, 0), DC - 1);
        }
        float up0 = 0.f, up1 = 0.f;
#pragma unroll
        for (int a = 0; a < 3; a++) {
            float r0s = 0.f, r1s = 0.f;
#pragma unroll
            for (int b = 0; b < 3; b++) {
                r0s += wc[b] * s_dn[0][sr[a]][sc[b]];
                r1s += wc[b] * s_dn[1][sr[a]][sc[b]];
            }
            up0 += wr[a] * r0s;
            up1 += wr[a] * r1s;
        }
        size_t o = (size_t)h * N + w;
        s_df[0][i][j] = __ldg(&cur0[o]) - up0 * (1.f / 64.f);
        s_df[1][i][j] = __ldg(&cur1[o]) - up1 * (1.f / 64.f);
    }
    __syncthreads();

    // |GX*diff| + |GY*diff| per image, then |m0 - m1|
    float val = 0.f;
    const int oy = oy0 + threadIdx.y, ox = ox0 + threadIdx.x;
    if (oy < N + 2 && ox < N + 2) {
        float m[2];
#pragma unroll
        for (int img = 0; img < 2; img++) {
            float d00 = s_df[img][threadIdx.y + 0][threadIdx.x + 0];
            float d01 = s_df[img][threadIdx.y + 0][threadIdx.x + 1];
            float d02 = s_df[img][threadIdx.y + 0][threadIdx.x + 2];
            float d10 = s_df[img][threadIdx.y + 1][threadIdx.x + 0];
            float d12 = s_df[img][threadIdx.y + 1][threadIdx.x + 2];
            float d20 = s_df[img][threadIdx.y + 2][threadIdx.x + 0];
            float d21 = s_df[img][threadIdx.y + 2][threadIdx.x + 1];
            float d22 = s_df[img][threadIdx.y + 2][threadIdx.x + 2];
            float gx = 2.f * (d00 - d02) + 4.f * (d10 - d12) + 2.f * (d20 - d22);
            float gy = 2.f * (d00 - d20) + 4.f * (d01 - d21) + 2.f * (d02 - d22);
            m[img] = fabsf(gx) + fabsf(gy);
        }
        val = fabsf(m[0] - m[1]);
    }

    // block reduction -> one double atomic per block
#pragma unroll
    for (int off = 16; off > 0; off >>= 1)
        val += __shfl_down_sync(0xffffffffu, val, off);
    if ((tid & 31) == 0) warpsum[tid >> 5] = val;
    __syncthreads();
    if (tid < 16) {
        float v = warpsum[tid];
#pragma unroll
        for (int off = 8; off > 0; off >>= 1)
            v += __shfl_down_sync(0xffffu, v, off);
        if (tid == 0) atomicAdd(&g_acc[lvl], (double)v);
    }
}

__global__ void finalize_kernel(float* __restrict__ out) {
    double l = g_acc[0] / ((double)PLANES * 514.0 * 514.0)
             + g_acc[1] / ((double)PLANES * 258.0 * 258.0)
             + g_acc[2] / ((double)PLANES * 130.0 * 130.0);
    out[0] = (float)l;
}

// -------------------------------------------------------------------------------
extern "C" void kernel_launch(void* const* d_in, const int* in_sizes, int n_in,
                              void* d_out, int out_size) {
    const float* inp = (const float*)d_in[0];
    const float* tgt = (const float*)d_in[1];
    // d_in[2] (gauss_kernel) is a fixed constant — baked into the kernels.
    float* out = (float*)d_out;

    zero_acc_kernel<<<1, 32>>>();

    // level 0 (512)
    down_kernel<<<dim3(8, 32, 96), dim3(32, 8)>>>(0, inp, tgt);
    loss_kernel<<<dim3(17, 33, PLANES), dim3(TX, TY)>>>(0, inp, tgt);
    // level 1 (256)
    down_kernel<<<dim3(4, 16, 96), dim3(32, 8)>>>(1, inp, tgt);
    loss_kernel<<<dim3(9, 17, PLANES), dim3(TX, TY)>>>(1, inp, tgt);
    // level 2 (128)
    down_kernel<<<dim3(2, 8, 96), dim3(32, 8)>>>(2, inp, tgt);
    loss_kernel<<<dim3(5, 9, PLANES), dim3(TX, TY)>>>(2, inp, tgt);

    finalize_kernel<<<1, 1>>>(out);
}